// round 6
// baseline (speedup 1.0000x reference)
#include <cuda_runtime.h>
#include <math.h>

// Problem constants (fixed by the dataset)
#define NPTS 65536
#define CH   128
#define NCLS 10
#define KNBR 27
#define OUTC 17   // 1 (ctr) + 6 (reg) + 10 (cls)

// sigmoid(s) > 0.15  <=>  s > log(0.15/0.85)
#define THRESH_LOGIT -1.7346010553881064f

#define SEM_BLOCKS 512
#define PTS_PER_SEMBLOCK (NPTS / SEM_BLOCKS)   // 128 pts/block, 16 per warp

__device__ __forceinline__ float elu1(float x) {
    return x > 0.f ? x : (expf(x) - 1.f);
}

// ---------------------------------------------------------------------------
// K1: pure store kernel (R1-proven: 14.2us @ 6.3TB/s, occ 76%).
// ---------------------------------------------------------------------------
__global__ void __launch_bounds__(256)
k_zero(float* __restrict__ out, long long nelem) {
    const long long n4 = nelem >> 2;
    float4* out4 = reinterpret_cast<float4*>(out);
    const long long idx    = (long long)blockIdx.x * blockDim.x + threadIdx.x;
    const long long stride = (long long)gridDim.x * blockDim.x;
    const float4 z = make_float4(0.f, 0.f, 0.f, 0.f);
    for (long long t = idx; t < n4; t += stride) out4[t] = z;
    for (long long t = (n4 << 2) + idx; t < nelem; t += stride) out[t] = 0.f;
}

// ---------------------------------------------------------------------------
// K2: sem + mask + (rare) heads, all block-local. 512 blocks x 256 threads,
// 128 points per block. Masks live in shared memory only — no globals, no
// reset, nothing that can diverge across graph replays.
// ---------------------------------------------------------------------------
__global__ void __launch_bounds__(256)
k_sem_heads(const float* __restrict__ feats,
            const int*   __restrict__ nbr,
            const float* __restrict__ Wsem,
            const float* __restrict__ bsem,
            const float* __restrict__ fo_w,
            const float* __restrict__ fo_g,
            const float* __restrict__ fo_b,
            const float* __restrict__ cls_out_w,
            const float* __restrict__ cls_out_g,
            const float* __restrict__ cls_out_b,
            const float* __restrict__ up_w,
            const float* __restrict__ up_g,
            const float* __restrict__ up_b,
            const float* __restrict__ fuse_w,
            const float* __restrict__ fuse_g,
            const float* __restrict__ fuse_b,
            const float* __restrict__ exp_w,
            const float* __restrict__ exp_g,
            const float* __restrict__ exp_b,
            const float* __restrict__ ctr_w,
            const float* __restrict__ reg_w,
            const float* __restrict__ cls_w,
            const float* __restrict__ cls_b,
            const float* __restrict__ scales,
            float* __restrict__ out) {
    __shared__ float4 sWt[NCLS * 32];   // Wsem transposed: sWt[c*32+g]=W[4g..4g+3][c]
    __shared__ float  sThr[NCLS];
    __shared__ unsigned short smask[PTS_PER_SEMBLOCK];
    // head-pipeline scratch (rare path only)
    __shared__ float sx[CH];
    __shared__ float cat[2 * CH];
    __shared__ float sec[CH];
    __shared__ float sof[CH];

    const int tid  = threadIdx.x;
    const int warp = tid >> 5;
    const int lane = tid & 31;

    if (tid < NCLS * 32) {
        const int c = tid >> 5, g = tid & 31;
        sWt[tid] = make_float4(Wsem[(4 * g + 0) * NCLS + c],
                               Wsem[(4 * g + 1) * NCLS + c],
                               Wsem[(4 * g + 2) * NCLS + c],
                               Wsem[(4 * g + 3) * NCLS + c]);
    }
    if (tid < NCLS) sThr[tid] = THRESH_LOGIT - bsem[tid];
    __syncthreads();

    const int blk_base = blockIdx.x * PTS_PER_SEMBLOCK;
    const int wbase    = blk_base + warp * 16;
    unsigned warp_any  = 0;

#pragma unroll
    for (int it = 0; it < 8; it++) {
        const int p0 = wbase + it * 2;
        const float4 f0 = reinterpret_cast<const float4*>(feats)[(long long)p0 * 32 + lane];
        const float4 f1 = reinterpret_cast<const float4*>(feats)[(long long)(p0 + 1) * 32 + lane];

        float s0[NCLS], s1[NCLS];
#pragma unroll
        for (int c = 0; c < NCLS; c++) {
            const float4 w = sWt[c * 32 + lane];
            s0[c] = f0.x * w.x + f0.y * w.y + f0.z * w.z + f0.w * w.w;
            s1[c] = f1.x * w.x + f1.y * w.y + f1.z * w.z + f1.w * w.w;
        }
        // folded reduction (validated R2/R4): xor16 on all 10, split classes
        // across half-warps, butterfly on 5, read partner set from lane16.
#pragma unroll
        for (int c = 0; c < NCLS; c++) {
            s0[c] += __shfl_xor_sync(0xffffffffu, s0[c], 16);
            s1[c] += __shfl_xor_sync(0xffffffffu, s1[c], 16);
        }
        const bool hi = (lane >= 16);
        float a5[5], b5[5];
#pragma unroll
        for (int k = 0; k < 5; k++) {
            a5[k] = hi ? s0[k + 5] : s0[k];
            b5[k] = hi ? s1[k + 5] : s1[k];
        }
#pragma unroll
        for (int off = 8; off; off >>= 1)
#pragma unroll
            for (int k = 0; k < 5; k++) {
                a5[k] += __shfl_xor_sync(0xffffffffu, a5[k], off);
                b5[k] += __shfl_xor_sync(0xffffffffu, b5[k], off);
            }
        float ua[5], ub[5];
#pragma unroll
        for (int k = 0; k < 5; k++) {
            ua[k] = __shfl_sync(0xffffffffu, a5[k], 16);
            ub[k] = __shfl_sync(0xffffffffu, b5[k], 16);
        }
        if (lane == 0) {
            unsigned m0 = 0, m1 = 0;
#pragma unroll
            for (int k = 0; k < 5; k++) {
                if (a5[k] > sThr[k])     m0 |= 1u << k;
                if (ua[k] > sThr[k + 5]) m0 |= 1u << (k + 5);
                if (b5[k] > sThr[k])     m1 |= 1u << k;
                if (ub[k] > sThr[k + 5]) m1 |= 1u << (k + 5);
            }
            // p0-blk_base is even: one 32-bit smem store covers both masks
            *reinterpret_cast<unsigned*>(&smask[p0 - blk_base]) = m0 | (m1 << 16);
            warp_any |= m0 | m1;
        }
    }
    if (!__syncthreads_or((int)warp_any)) return;   // hot path: exit

    // ---------------- rare path: full head pipeline for flagged pairs -------
    const int j = tid;   // channel id where j < CH
    for (int t = 0; t < PTS_PER_SEMBLOCK; t++) {
        unsigned m = smask[t];
        if (!m) continue;
        const int i = blk_base + t;

        // offset_features[i] = ELU(affine(sum_k feats[nbr[i,k]] @ fo_w[k]))
        float acc = 0.f;
        for (int k = 0; k < KNBR; k++) {
            const int nb = nbr[i * KNBR + k];
            __syncthreads();
            if (j < CH) sx[j] = feats[(long long)nb * CH + j];
            __syncthreads();
            if (j < CH) {
                const float* W = fo_w + (long long)k * CH * CH;
                for (int mm = 0; mm < CH; mm++) acc += sx[mm] * W[mm * CH + j];
            }
        }
        if (j < CH) sof[j] = elu1(acc * fo_g[j] + fo_b[j]);

        while (m) {
            const int c = __ffs(m) - 1;
            m &= (m - 1);
            for (int half = 0; half < 2; half++) {
                __syncthreads();
                if (j < CH) sx[j] = (half == 0) ? sof[j]
                                                : feats[(long long)i * CH + j];
                __syncthreads();
                if (j < CH) {   // hc
                    const float* W = cls_out_w + (long long)c * CH * CH;
                    float a = 0.f;
                    for (int mm = 0; mm < CH; mm++) a += sx[mm] * W[mm * CH + j];
                    a = a * cls_out_g[c * CH + j] + cls_out_b[c * CH + j];
                    cat[j] = elu1(a);
                }
                __syncthreads();
                if (j < CH) {   // uc
                    const float* W = up_w + (long long)c * CH * CH;
                    float a = 0.f;
                    for (int mm = 0; mm < CH; mm++) a += cat[mm] * W[mm * CH + j];
                    a = a * up_g[c * CH + j] + up_b[c * CH + j];
                    cat[CH + j] = elu1(a);
                }
                __syncthreads();
                float fc = 0.f;
                if (j < CH) {   // fc
                    const float* W = fuse_w + (long long)c * 2 * CH * CH;
                    float a = 0.f;
                    for (int mm = 0; mm < 2 * CH; mm++) a += cat[mm] * W[mm * CH + j];
                    a = a * fuse_g[c * CH + j] + fuse_b[c * CH + j];
                    fc = elu1(a);
                }
                __syncthreads();
                if (j < CH) sx[j] = fc;
                __syncthreads();
                if (j < CH) {   // ec
                    const float* W = exp_w + (long long)c * CH * CH;
                    float a = 0.f;
                    for (int mm = 0; mm < CH; mm++) a += sx[mm] * W[mm * CH + j];
                    a = a * exp_g[c * CH + j] + exp_b[c * CH + j];
                    sec[j] = elu1(a);
                }
                __syncthreads();

                const long long row = (half == 0) ? (long long)i
                                                  : (long long)(NPTS + i);
                float* orow = out + ((long long)c * 2 * NPTS + row) * OUTC;
                if (j == 0) {
                    float s = 0.f;
                    for (int mm = 0; mm < CH; mm++) s += sec[mm] * ctr_w[mm];
                    orow[0] = s;
                } else if (j < 7) {
                    const int r = j - 1;
                    float s = 0.f;
                    for (int mm = 0; mm < CH; mm++) s += sec[mm] * reg_w[mm * 6 + r];
                    orow[j] = expf(scales[c] * s);
                } else if (j < 17) {
                    const int q = j - 7;
                    float s = 0.f;
                    for (int mm = 0; mm < CH; mm++) s += sec[mm] * cls_w[mm * NCLS + q];
                    orow[j] = s + cls_b[q];
                }
            }
        }
    }
}

// ---------------------------------------------------------------------------
// Launch (single stream, launch-only: graph-capture safe).
// Input order per metadata: coords, feats, nbr, Wsem, bsem, off_w1,g1,b1,
// off_w2,g2,b2, off_w3, fo_w,g,b, cls_out_w,g,b, up_w,g,b, fuse_w,g,b,
// exp_w,g,b, ctr_w, reg_w, cls_w, cls_b, scales.
// Offset-MLP branch (5..11) and coords (0) are dead w.r.t. the output tensor.
// ---------------------------------------------------------------------------
extern "C" void kernel_launch(void* const* d_in, const int* in_sizes, int n_in,
                              void* d_out, int out_size) {
    const float* feats     = (const float*)d_in[1];
    const int*   nbr       = (const int*)  d_in[2];
    const float* Wsem      = (const float*)d_in[3];
    const float* bsem      = (const float*)d_in[4];
    const float* fo_w      = (const float*)d_in[12];
    const float* fo_g      = (const float*)d_in[13];
    const float* fo_b      = (const float*)d_in[14];
    const float* cls_out_w = (const float*)d_in[15];
    const float* cls_out_g = (const float*)d_in[16];
    const float* cls_out_b = (const float*)d_in[17];
    const float* up_w      = (const float*)d_in[18];
    const float* up_g      = (const float*)d_in[19];
    const float* up_b      = (const float*)d_in[20];
    const float* fuse_w    = (const float*)d_in[21];
    const float* fuse_g    = (const float*)d_in[22];
    const float* fuse_b    = (const float*)d_in[23];
    const float* exp_w     = (const float*)d_in[24];
    const float* exp_g     = (const float*)d_in[25];
    const float* exp_b     = (const float*)d_in[26];
    const float* ctr_w     = (const float*)d_in[27];
    const float* reg_w     = (const float*)d_in[28];
    const float* cls_w     = (const float*)d_in[29];
    const float* cls_b     = (const float*)d_in[30];
    const float* scales    = (const float*)d_in[31];
    float* out = (float*)d_out;

    const long long nelem = (long long)out_size;

    k_zero<<<4096, 256>>>(out, nelem);

    k_sem_heads<<<SEM_BLOCKS, 256>>>(feats, nbr, Wsem, bsem,
                                     fo_w, fo_g, fo_b,
                                     cls_out_w, cls_out_g, cls_out_b,
                                     up_w, up_g, up_b,
                                     fuse_w, fuse_g, fuse_b,
                                     exp_w, exp_g, exp_b,
                                     ctr_w, reg_w, cls_w, cls_b, scales, out);
}